// round 12
// baseline (speedup 1.0000x reference)
#include <cuda_runtime.h>
#include <math.h>
#include <stdint.h>

// Fixed dataset shapes: N=1024, P=4, G=20000 (tolerates P==4, G<=G_MAX, N<=N_MAX)
#define G_MAX 20480
#define N_MAX 1024
#define CH    512          // genes per chunk (phase A and B tiles)
#define NC_MAX 48          // max gene chunks
#define RA    16           // phase A rows per tile
#define RB    8            // phase B rows per tile
#define GB    592          // grid blocks = 148 SM x 4 (co-resident, <= GB300 capacity)

// ---- device scratch (static; no allocations) ----
__device__ __align__(16) float g_r[G_MAX];     // 1/softplus(phi)  (raw)
__device__ __align__(16) float g_C2[G_MAX];    // per-gene const, base-2 units
__device__ __align__(16) float g_mu2[G_MAX];   // mu * log2e
__device__ __align__(16) float g_q0[G_MAX];    // beta rows * log2e
__device__ __align__(16) float g_q1[G_MAX];
__device__ __align__(16) float g_q2[G_MAX];
__device__ __align__(16) float g_q3[G_MAX];
__device__ float  g_Zp[NC_MAX * N_MAX];        // per-(chunk,row) sum exp(lu)
__device__ float  g_Sp[NC_MAX * N_MAX];        // per-(chunk,row) sum Y
__device__ double g_prior[NC_MAX];             // per-chunk prior partial (nats)
__device__ double g_part[GB];                  // per-block likelihood partial (nats)
__device__ unsigned g_bar;                     // grid barrier arrivals (monotone)
__device__ unsigned g_ticket;                  // final-reduction ticket (monotone)

#define NORM_CONST   1.6120857137646180f       // 0.5*log(8*pi), s=2 normal prior
#define HALF_LOG_2PI 0.9189385332046727f
#define LOG2E        1.4426950408889634f
#define LN2          0.6931471805599453
#define SER_K        0.12022458674074694f      // LOG2E / 12
#define SHIFT4       5.7707801635558537f       // 4 * LOG2E

// raw MUFU ops
__device__ __forceinline__ float ex2a(float a){ float r; asm("ex2.approx.ftz.f32 %0,%1;":"=f"(r):"f"(a)); return r; }
__device__ __forceinline__ float lg2a(float a){ float r; asm("lg2.approx.ftz.f32 %0,%1;":"=f"(r):"f"(a)); return r; }
__device__ __forceinline__ float rcpa(float a){ float r; asm("rcp.approx.ftz.f32 %0,%1;":"=f"(r):"f"(a)); return r; }

// packed f32x2 ops (sm_103a)
typedef unsigned long long u64;
__device__ __forceinline__ u64 pk2(float lo, float hi){ u64 r; asm("mov.b64 %0,{%1,%2};":"=l"(r):"f"(lo),"f"(hi)); return r; }
__device__ __forceinline__ void upk2(u64 v, float& lo, float& hi){ asm("mov.b64 {%0,%1},%2;":"=f"(lo),"=f"(hi):"l"(v)); }
__device__ __forceinline__ u64 fma2(u64 a,u64 b,u64 c){ u64 r; asm("fma.rn.f32x2 %0,%1,%2,%3;":"=l"(r):"l"(a),"l"(b),"l"(c)); return r; }
__device__ __forceinline__ u64 add2(u64 a,u64 b){ u64 r; asm("add.rn.f32x2 %0,%1,%2;":"=l"(r):"l"(a),"l"(b)); return r; }
__device__ __forceinline__ u64 sub2(u64 a,u64 b){ u64 r; asm("sub.rn.f32x2 %0,%1,%2;":"=l"(r):"l"(a),"l"(b)); return r; }
__device__ __forceinline__ u64 mul2(u64 a,u64 b){ u64 r; asm("mul.rn.f32x2 %0,%1,%2;":"=l"(r):"l"(a),"l"(b)); return r; }

// ---- block reduce for double (256 threads) ----
__device__ __forceinline__ double blk_reduce256(double v, double* sRed) {
    int t = threadIdx.x, lane = t & 31, wid = t >> 5;
    #pragma unroll
    for (int off = 16; off; off >>= 1)
        v += __shfl_down_sync(0xffffffffu, v, off);
    if (lane == 0) sRed[wid] = v;
    __syncthreads();
    if (t < 8) {
        v = sRed[t];
        #pragma unroll
        for (int off = 4; off; off >>= 1)
            v += __shfl_down_sync(0x000000ffu, v, off);
    }
    return v;  // valid in thread 0
}

// ---- scalar NB core (tail path), always-shift Stirling, base-2 units ----
__device__ __forceinline__ float nb_elem_s(const float* xr, float wn, float y,
                                           float b0, float b1, float b2, float b3,
                                           float mug, float r,
                                           const float* __restrict__ sT) {
    float tt = fmaf(xr[0], b0, fmaf(xr[1], b1, fmaf(xr[2], b2, fmaf(xr[3], b3, mug)))) + wn;
    float m  = ex2a(tt);
    float lg = lg2a(r + m);
    float x  = y + r;
    float p  = (x * (x + 1.f)) * ((x + 2.f) * (x + 3.f));
    float xs = x + 4.f;
    float extra = -lg2a(p) - SHIFT4;
    float z  = rcpa(xs);
    float stir = fmaf(xs - 0.5f, lg2a(xs), fmaf(z, SER_K, extra));
    return stir - sT[(int)y] + fmaf(y, tt, -x * lg);
}

// =========================================================================
// Fused persistent kernel: phase A (Z/S partials + setup + priors) ->
// software grid barrier -> phase B (NB likelihood, Y hot in L2) -> reduce.
// grid = GB blocks x 256 threads, co-resident by construction.
// =========================================================================
template <bool VEC>
__global__ void __launch_bounds__(256, 4) k_fused(
        const float* __restrict__ X, const float* __restrict__ Y,
        const float* __restrict__ mu, const float* __restrict__ beta,
        const float* __restrict__ phi, float* __restrict__ out,
        int N, int G, int NCHUNK, int nTilesA, int nTilesB) {
    __shared__ float smu[CH], sb0[CH], sb1[CH], sb2[CH], sb3[CH];
    __shared__ float sT[512];
    __shared__ u64   sxd[RB][5];
    __shared__ double sRed[8];
    __shared__ int    sLast;

    int t = threadIdx.x, bid = blockIdx.x;
    int w = t >> 5, lane = t & 31;

    // local lgamma table (phase B): sT[k] = (lgamma(k+1)+k)*log2e
    for (int i = t; i < 512; i += 256)
        sT[i] = (lgammaf((float)i + 1.f) + (float)i) * LOG2E;

    // ---------------- Phase A ----------------
    for (int tile = bid; tile < nTilesA; tile += GB) {
        __syncthreads();                     // protect smem re-stage
        int chunk  = tile % NCHUNK;
        int rowblk = tile / NCHUNK;
        int gbase  = chunk * CH;
        int gmax   = min(CH, G - gbase);
        for (int i = t; i < CH; i += 256) {
            int g = gbase + i;
            bool v = (i < gmax);
            smu[i] = v ? __ldg(mu + g)         * LOG2E : -1e30f;
            sb0[i] = v ? __ldg(beta + g)       * LOG2E : 0.f;
            sb1[i] = v ? __ldg(beta + G + g)   * LOG2E : 0.f;
            sb2[i] = v ? __ldg(beta + 2*G + g) * LOG2E : 0.f;
            sb3[i] = v ? __ldg(beta + 3*G + g) * LOG2E : 0.f;
        }
        __syncthreads();

        int n0 = rowblk * RA + w * 2;        // 8 warps x 2 rows = 16 rows
        float4 xr[2]; const float* Yr[2];
        #pragma unroll
        for (int r = 0; r < 2; r++) {
            int n = min(n0 + r, N - 1);
            xr[r] = ((const float4*)X)[n];
            Yr[r] = Y + (size_t)n * G + gbase;
        }
        float ae[2] = {0.f, 0.f}, ay[2] = {0.f, 0.f};
        #pragma unroll
        for (int it = 0; it < CH / 128; it++) {
            int j  = it * 32 + lane;
            int g4 = j * 4;
            float4 m4 = ((const float4*)smu)[j];
            float4 a0 = ((const float4*)sb0)[j];
            float4 a1 = ((const float4*)sb1)[j];
            float4 a2 = ((const float4*)sb2)[j];
            float4 a3 = ((const float4*)sb3)[j];
            #pragma unroll
            for (int r = 0; r < 2; r++) {
                float4 y;
                if (g4 + 3 < gmax) {
                    if (VEC) y = *(const float4*)(Yr[r] + g4);
                    else { y.x = Yr[r][g4]; y.y = Yr[r][g4+1];
                           y.z = Yr[r][g4+2]; y.w = Yr[r][g4+3]; }
                } else {
                    y.x = (g4+0 < gmax) ? Yr[r][g4+0] : 0.f;
                    y.y = (g4+1 < gmax) ? Yr[r][g4+1] : 0.f;
                    y.z = (g4+2 < gmax) ? Yr[r][g4+2] : 0.f;
                    y.w = (g4+3 < gmax) ? Yr[r][g4+3] : 0.f;
                }
                float l0 = fmaf(xr[r].x, a0.x, fmaf(xr[r].y, a1.x, fmaf(xr[r].z, a2.x, fmaf(xr[r].w, a3.x, m4.x))));
                float l1 = fmaf(xr[r].x, a0.y, fmaf(xr[r].y, a1.y, fmaf(xr[r].z, a2.y, fmaf(xr[r].w, a3.y, m4.y))));
                float l2 = fmaf(xr[r].x, a0.z, fmaf(xr[r].y, a1.z, fmaf(xr[r].z, a2.z, fmaf(xr[r].w, a3.z, m4.z))));
                float l3 = fmaf(xr[r].x, a0.w, fmaf(xr[r].y, a1.w, fmaf(xr[r].z, a2.w, fmaf(xr[r].w, a3.w, m4.w))));
                ae[r] += (ex2a(l0) + ex2a(l1)) + (ex2a(l2) + ex2a(l3));
                ay[r] += (y.x + y.y) + (y.z + y.w);
            }
        }
        #pragma unroll
        for (int r = 0; r < 2; r++) {
            float e = ae[r], s = ay[r];
            #pragma unroll
            for (int off = 16; off; off >>= 1) {
                e += __shfl_down_sync(0xffffffffu, e, off);
                s += __shfl_down_sync(0xffffffffu, s, off);
            }
            if (lane == 0 && n0 + r < N) {
                g_Zp[chunk * N_MAX + n0 + r] = e;
                g_Sp[chunk * N_MAX + n0 + r] = s;
            }
        }

        // per-gene setup + priors (exactly once per chunk: rowblk==0 tiles)
        if (rowblk == 0) {
            double lp = 0.0;
            for (int i = t; i < gmax; i += 256) {
                int g = gbase + i;
                float ph = __ldg(phi + g);
                float sp = fmaxf(ph, 0.f) + log1pf(expf(-fabsf(ph)));
                float r  = 1.f / sp;
                g_r[g]   = r;
                g_C2[g]  = (r * logf(r) - lgammaf(r) - r + HALF_LOG_2PI) * LOG2E;
                g_mu2[g] = smu[i];
                g_q0[g]  = sb0[i];
                g_q1[g]  = sb1[i];
                g_q2[g]  = sb2[i];
                g_q3[g]  = sb3[i];
                float m  = __ldg(mu + g);
                float b0 = __ldg(beta + g),       b1 = __ldg(beta + G + g);
                float b2 = __ldg(beta + 2*G + g), b3 = __ldg(beta + 3*G + g);
                lp += (double)(logf(sp) - sp - NORM_CONST - 0.125f * m * m);
                lp += (double)(-4.f * NORM_CONST
                               - 0.125f * ((b0*b0 + b1*b1) + (b2*b2 + b3*b3)));
            }
            __syncthreads();
            double tot = blk_reduce256(lp, sRed);
            if (t == 0) g_prior[chunk] = tot;
        }
    }

    // ---------------- grid barrier (replay-safe, monotone counter) --------
    __threadfence();                         // publish this thread's writes
    __syncthreads();
    if (t == 0) {
        unsigned tk = atomicAdd(&g_bar, 1u);
        unsigned target = (tk / GB + 1u) * GB;
        while (*(volatile unsigned*)&g_bar < target) __nanosleep(128);
    }
    __syncthreads();
    __threadfence();                         // acquire side

    // ---------------- Phase B ----------------
    const u64 C1e = pk2(1.f, 1.f),  C2e = pk2(2.f, 2.f);
    const u64 C3e = pk2(3.f, 3.f),  C4e = pk2(4.f, 4.f);
    const u64 CHe = pk2(-0.5f, -0.5f), CSe = pk2(SER_K, SER_K);
    const u64 CN4e = pk2(-SHIFT4, -SHIFT4), CN1e = pk2(-1.f, -1.f);
    int nGB = NCHUNK;                        // 512-gene tiles

    double d = 0.0;
    for (int tile = bid; tile < nTilesB; tile += GB) {
        int gb = tile % nGB, rowblk = tile / nGB;
        int row0 = rowblk * RB;
        int rh   = min(RB, N - row0);
        __syncthreads();
        if (t < RB) {
            int n = min(row0 + t, N - 1);
            float4 xv = ((const float4*)X)[n];
            float Z = 0.f, S = 0.f;
            for (int c = 0; c < NCHUNK; c++) {
                Z += g_Zp[c * N_MAX + n];
                S += g_Sp[c * N_MAX + n];
            }
            float wn = lg2a(S) - lg2a(Z);
            sxd[t][0] = pk2(xv.x, xv.x);
            sxd[t][1] = pk2(xv.y, xv.y);
            sxd[t][2] = pk2(xv.z, xv.z);
            sxd[t][3] = pk2(xv.w, xv.w);
            sxd[t][4] = pk2(wn, wn);
        }
        __syncthreads();

        int gp = gb * CH + t * 2;
        if (gp >= G) continue;
        bool full = (gp + 1 < G);
        int gc1 = min(gp + 1, G - 1);
        float r0 = g_r[gp], r1 = g_r[gc1];

        {   // fold per-gene constants (base-2)
            float csum = g_C2[gp];
            if (full) csum += g_C2[gc1];
            d += (double)rh * (double)csum;
        }

        if (VEC && full && rh == RB) {
            u64 P0 = pk2(g_q0[gp], g_q0[gc1]);
            u64 P1 = pk2(g_q1[gp], g_q1[gc1]);
            u64 P2 = pk2(g_q2[gp], g_q2[gc1]);
            u64 P3 = pk2(g_q3[gp], g_q3[gc1]);
            u64 M2 = pk2(g_mu2[gp], g_mu2[gc1]);
            u64 R2 = pk2(r0, r1);
            u64 acc2 = pk2(0.f, 0.f);
            const float* Yp = Y + (size_t)row0 * G + gp;
            float2 ycur = *(const float2*)Yp; Yp += G;
            #pragma unroll
            for (int i = 0; i < RB; i++) {
                float2 ynxt = ycur;
                if (i + 1 < RB) { ynxt = *(const float2*)Yp; Yp += G; }
                u64 y2 = pk2(ycur.x, ycur.y);
                u64 tt2 = add2(fma2(sxd[i][0], P0,
                            fma2(sxd[i][1], P1,
                            fma2(sxd[i][2], P2,
                            fma2(sxd[i][3], P3, M2)))), sxd[i][4]);
                float t0, t1; upk2(tt2, t0, t1);
                u64 lgrm = pk2(lg2a(r0 + ex2a(t0)), lg2a(r1 + ex2a(t1)));
                u64 x2  = add2(y2, R2);
                u64 p2  = mul2(mul2(x2, add2(x2, C1e)),
                               mul2(add2(x2, C2e), add2(x2, C3e)));
                float pA, pB; upk2(p2, pA, pB);
                u64 lp2 = pk2(lg2a(pA), lg2a(pB));
                u64 xs2 = add2(x2, C4e);
                float xA, xB; upk2(xs2, xA, xB);
                u64 z2   = pk2(rcpa(xA), rcpa(xB));
                u64 lxs2 = pk2(lg2a(xA), lg2a(xB));
                u64 extra2 = fma2(lp2, CN1e, CN4e);
                u64 ser2   = fma2(z2, CSe, extra2);
                u64 stir2  = fma2(add2(xs2, CHe), lxs2, ser2);
                u64 sT2 = pk2(sT[(int)ycur.x], sT[(int)ycur.y]);
                u64 res = sub2(stir2, sT2);
                res = fma2(y2, tt2, res);
                res = sub2(res, mul2(x2, lgrm));
                acc2 = add2(acc2, res);
                ycur = ynxt;
            }
            float aLo, aHi; upk2(acc2, aLo, aHi);
            d += (double)aLo + (double)aHi;
        } else {
            // scalar tail path (ragged rows / genes / misaligned)
            for (int i = 0; i < rh; i++) {
                float xs[4], wns, dummy;
                upk2(sxd[i][0], xs[0], dummy);
                upk2(sxd[i][1], xs[1], dummy);
                upk2(sxd[i][2], xs[2], dummy);
                upk2(sxd[i][3], xs[3], dummy);
                upk2(sxd[i][4], wns, dummy);
                const float* Yp = Y + (size_t)(row0 + i) * G;
                float e0 = nb_elem_s(xs, wns, Yp[gp],
                                     g_q0[gp], g_q1[gp], g_q2[gp], g_q3[gp],
                                     g_mu2[gp], r0, sT);
                d += (double)e0;
                if (full) {
                    float e1 = nb_elem_s(xs, wns, Yp[gc1],
                                         g_q0[gc1], g_q1[gc1], g_q2[gc1], g_q3[gc1],
                                         g_mu2[gc1], r1, sT);
                    d += (double)e1;
                }
            }
        }
    }
    d *= LN2;                                // base-2 -> nats

    // ---------------- final reduction ----------------
    __syncthreads();
    double bsum = blk_reduce256(d, sRed);
    if (t == 0) {
        g_part[bid] = bsum;
        __threadfence();
        unsigned old = atomicAdd(&g_ticket, 1u);
        sLast = ((old % (unsigned)GB) == (unsigned)(GB - 1));
    }
    __syncthreads();
    if (sLast) {
        double s = 0.0;
        for (int i = t; i < GB; i += 256) s += g_part[i];
        for (int c = t; c < NCHUNK; c += 256) s += g_prior[c];
        __syncthreads();
        double tot = blk_reduce256(s, sRed);
        if (t == 0) out[0] = (float)tot;
    }
}

extern "C" void kernel_launch(void* const* d_in, const int* in_sizes, int n_in,
                              void* d_out, int out_size) {
    const float* X    = (const float*)d_in[0];
    const float* Y    = (const float*)d_in[1];
    const float* mu   = (const float*)d_in[2];
    const float* beta = (const float*)d_in[3];
    const float* phi  = (const float*)d_in[4];
    float* out = (float*)d_out;

    int G = in_sizes[2];          // 20000
    int N = in_sizes[1] / G;      // 1024

    int NCHUNK  = (G + CH - 1) / CH;                 // 40
    int nTilesA = NCHUNK * ((N + RA - 1) / RA);      // 40*64  = 2560
    int nTilesB = NCHUNK * ((N + RB - 1) / RB);      // 40*128 = 5120
    bool vec = ((G & 3) == 0) && ((((unsigned long long)Y) & 15ull) == 0ull);

    if (vec) k_fused<true><<<GB, 256>>>(X, Y, mu, beta, phi, out, N, G, NCHUNK, nTilesA, nTilesB);
    else     k_fused<false><<<GB, 256>>>(X, Y, mu, beta, phi, out, N, G, NCHUNK, nTilesA, nTilesB);
}

// round 13
// speedup vs baseline: 1.1462x; 1.1462x over previous
#include <cuda_runtime.h>
#include <math.h>
#include <stdint.h>

// Fixed dataset shapes: N=1024, P=4, G=20000 (tolerates N%32==0, P==4, G<=G_MAX)
#define G_MAX 20480
#define N_MAX 1024
#define CH    512          // genes per pass1 chunk
#define NC_MAX 48          // max gene chunks
#define RP2   16           // rows per pass2 block (2 half-batches of 8)
#define HB    8            // half-batch rows (independent loads in flight)
#define MAX_B2 8192        // max pass2 blocks

// ---- device scratch (static; no allocations) ----
__device__ __align__(16) float g_r[G_MAX];     // 1/softplus(phi)  (raw)
__device__ __align__(16) float g_C2[G_MAX];    // per-gene const, base-2 units
__device__ __align__(16) float g_mu2[G_MAX];   // mu * log2e
__device__ __align__(16) float g_q0[G_MAX];    // beta rows * log2e
__device__ __align__(16) float g_q1[G_MAX];
__device__ __align__(16) float g_q2[G_MAX];
__device__ __align__(16) float g_q3[G_MAX];
__device__ float  g_tab[512];                  // (lgamma(k+1)+k) * log2e
__device__ float  g_Zp[NC_MAX * N_MAX];        // per-(chunk,row) sum exp(lu)
__device__ float  g_Sp[NC_MAX * N_MAX];        // per-(chunk,row) sum Y
__device__ double g_prior[NC_MAX];             // per-chunk prior partial (nats)
__device__ double g_part[MAX_B2];              // per-pass2-block partial (nats)
__device__ unsigned g_ticket;                  // monotone ticket (mod #blocks)

#define NORM_CONST   1.6120857137646180f       // 0.5*log(8*pi), s=2 normal prior
#define HALF_LOG_2PI 0.9189385332046727f
#define LOG2E        1.4426950408889634f
#define LN2          0.6931471805599453
#define SER_K        0.12022458674074694f      // LOG2E / 12
#define SHIFT4       5.7707801635558537f       // 4 * LOG2E

// raw MUFU ops
__device__ __forceinline__ float ex2a(float a){ float r; asm("ex2.approx.ftz.f32 %0,%1;":"=f"(r):"f"(a)); return r; }
__device__ __forceinline__ float lg2a(float a){ float r; asm("lg2.approx.ftz.f32 %0,%1;":"=f"(r):"f"(a)); return r; }
__device__ __forceinline__ float rcpa(float a){ float r; asm("rcp.approx.ftz.f32 %0,%1;":"=f"(r):"f"(a)); return r; }

// packed f32x2 ops (sm_103a)
typedef unsigned long long u64;
__device__ __forceinline__ u64 pk2(float lo, float hi){ u64 r; asm("mov.b64 %0,{%1,%2};":"=l"(r):"f"(lo),"f"(hi)); return r; }
__device__ __forceinline__ void upk2(u64 v, float& lo, float& hi){ asm("mov.b64 {%0,%1},%2;":"=f"(lo),"=f"(hi):"l"(v)); }
__device__ __forceinline__ u64 fma2(u64 a,u64 b,u64 c){ u64 r; asm("fma.rn.f32x2 %0,%1,%2,%3;":"=l"(r):"l"(a),"l"(b),"l"(c)); return r; }
__device__ __forceinline__ u64 add2(u64 a,u64 b){ u64 r; asm("add.rn.f32x2 %0,%1,%2;":"=l"(r):"l"(a),"l"(b)); return r; }
__device__ __forceinline__ u64 sub2(u64 a,u64 b){ u64 r; asm("sub.rn.f32x2 %0,%1,%2;":"=l"(r):"l"(a),"l"(b)); return r; }
__device__ __forceinline__ u64 mul2(u64 a,u64 b){ u64 r; asm("mul.rn.f32x2 %0,%1,%2;":"=l"(r):"l"(a),"l"(b)); return r; }

// ---- block reduce for double (256 threads) ----
__device__ __forceinline__ double blk_reduce256(double v, double* sRed) {
    int t = threadIdx.x, lane = t & 31, wid = t >> 5;
    #pragma unroll
    for (int off = 16; off; off >>= 1)
        v += __shfl_down_sync(0xffffffffu, v, off);
    if (lane == 0) sRed[wid] = v;
    __syncthreads();
    if (t < 8) {
        v = sRed[t];
        #pragma unroll
        for (int off = 4; off; off >>= 1)
            v += __shfl_down_sync(0x000000ffu, v, off);
    }
    return v;  // valid in thread 0
}

// ---- scalar NB core (tail path), always-shift Stirling, base-2 units ----
__device__ __forceinline__ float nb_elem_s(const float* xr, float wn, float y,
                                           float b0, float b1, float b2, float b3,
                                           float mug, float r,
                                           const float* __restrict__ sT) {
    float tt = fmaf(xr[0], b0, fmaf(xr[1], b1, fmaf(xr[2], b2, fmaf(xr[3], b3, mug)))) + wn;
    float m  = ex2a(tt);
    float lg = lg2a(r + m);
    float x  = y + r;
    float p  = (x * (x + 1.f)) * ((x + 2.f) * (x + 3.f));
    float xs = x + 4.f;
    float extra = -lg2a(p) - SHIFT4;
    float z  = rcpa(xs);
    float stir = fmaf(xs - 0.5f, lg2a(xs), fmaf(z, SER_K, extra));
    return stir - sT[(int)y] + fmaf(y, tt, -x * lg);
}

// =========================================================================
// Pass 1: per-(chunk,row) sumexp(lu) and sum(Y); by==0 blocks also do the
// per-gene setup (r, C2, scaled params), priors, and the lgamma table.
// grid (NCHUNK, N/32), 256 threads; warp w owns rows by*32 + 4w .. +3
// =========================================================================
template <bool VEC>
__global__ void __launch_bounds__(256) k_pass1(
        const float* __restrict__ X, const float* __restrict__ Y,
        const float* __restrict__ mu, const float* __restrict__ beta,
        const float* __restrict__ phi, int N, int G) {
    __shared__ float smu[CH], sb0[CH], sb1[CH], sb2[CH], sb3[CH];
    __shared__ double sRed[8];

    int gbase = blockIdx.x * CH;
    int gmax  = min(CH, G - gbase);
    for (int i = threadIdx.x; i < CH; i += 256) {
        int g = gbase + i;
        bool v = (i < gmax);
        smu[i] = v ? __ldg(mu + g)         * LOG2E : -1e30f;
        sb0[i] = v ? __ldg(beta + g)       * LOG2E : 0.f;
        sb1[i] = v ? __ldg(beta + G + g)   * LOG2E : 0.f;
        sb2[i] = v ? __ldg(beta + 2*G + g) * LOG2E : 0.f;
        sb3[i] = v ? __ldg(beta + 3*G + g) * LOG2E : 0.f;
    }
    __syncthreads();

    int w = threadIdx.x >> 5, lane = threadIdx.x & 31;
    int n0 = blockIdx.y * 32 + w * 4;
    const float4* X4 = (const float4*)X;
    float4 xr[4];
    const float* Yr[4];
    #pragma unroll
    for (int r = 0; r < 4; r++) {
        int n = min(n0 + r, N - 1);
        xr[r] = X4[n];
        Yr[r] = Y + (size_t)n * G + gbase;
    }

    float ae[4] = {0.f, 0.f, 0.f, 0.f};
    float ay[4] = {0.f, 0.f, 0.f, 0.f};

    #pragma unroll 2
    for (int it = 0; it < CH / 128; it++) {
        int j  = it * 32 + lane;
        int g4 = j * 4;
        float4 m4 = ((const float4*)smu)[j];
        float4 a0 = ((const float4*)sb0)[j];
        float4 a1 = ((const float4*)sb1)[j];
        float4 a2 = ((const float4*)sb2)[j];
        float4 a3 = ((const float4*)sb3)[j];
        #pragma unroll
        for (int r = 0; r < 4; r++) {
            float4 y;
            if (g4 + 3 < gmax) {
                if (VEC) y = *(const float4*)(Yr[r] + g4);
                else { y.x = Yr[r][g4]; y.y = Yr[r][g4+1];
                       y.z = Yr[r][g4+2]; y.w = Yr[r][g4+3]; }
            } else {
                y.x = (g4+0 < gmax) ? Yr[r][g4+0] : 0.f;
                y.y = (g4+1 < gmax) ? Yr[r][g4+1] : 0.f;
                y.z = (g4+2 < gmax) ? Yr[r][g4+2] : 0.f;
                y.w = (g4+3 < gmax) ? Yr[r][g4+3] : 0.f;
            }
            float l0 = fmaf(xr[r].x, a0.x, fmaf(xr[r].y, a1.x, fmaf(xr[r].z, a2.x, fmaf(xr[r].w, a3.x, m4.x))));
            float l1 = fmaf(xr[r].x, a0.y, fmaf(xr[r].y, a1.y, fmaf(xr[r].z, a2.y, fmaf(xr[r].w, a3.y, m4.y))));
            float l2 = fmaf(xr[r].x, a0.z, fmaf(xr[r].y, a1.z, fmaf(xr[r].z, a2.z, fmaf(xr[r].w, a3.z, m4.z))));
            float l3 = fmaf(xr[r].x, a0.w, fmaf(xr[r].y, a1.w, fmaf(xr[r].z, a2.w, fmaf(xr[r].w, a3.w, m4.w))));
            ae[r] += (ex2a(l0) + ex2a(l1)) + (ex2a(l2) + ex2a(l3));
            ay[r] += (y.x + y.y) + (y.z + y.w);
        }
    }

    #pragma unroll
    for (int r = 0; r < 4; r++) {
        float e = ae[r], s = ay[r];
        #pragma unroll
        for (int off = 16; off; off >>= 1) {
            e += __shfl_down_sync(0xffffffffu, e, off);
            s += __shfl_down_sync(0xffffffffu, s, off);
        }
        if (lane == 0 && n0 + r < N) {
            g_Zp[blockIdx.x * N_MAX + n0 + r] = e;
            g_Sp[blockIdx.x * N_MAX + n0 + r] = s;
        }
    }

    // ---- setup + priors (one row-block per chunk) ----
    if (blockIdx.y == 0) {
        double lp = 0.0;
        for (int i = threadIdx.x; i < gmax; i += 256) {
            int g = gbase + i;
            float ph = __ldg(phi + g);
            float sp = fmaxf(ph, 0.f) + log1pf(expf(-fabsf(ph)));  // softplus
            float r  = 1.f / sp;
            g_r[g]   = r;
            g_C2[g]  = (r * logf(r) - lgammaf(r) - r + HALF_LOG_2PI) * LOG2E;
            g_mu2[g] = smu[i];            // already * log2e
            g_q0[g]  = sb0[i];
            g_q1[g]  = sb1[i];
            g_q2[g]  = sb2[i];
            g_q3[g]  = sb3[i];
            float m  = __ldg(mu + g);
            float b0 = __ldg(beta + g),       b1 = __ldg(beta + G + g);
            float b2 = __ldg(beta + 2*G + g), b3 = __ldg(beta + 3*G + g);
            lp += (double)(logf(sp) - sp - NORM_CONST - 0.125f * m * m);
            lp += (double)(-4.f * NORM_CONST
                           - 0.125f * ((b0*b0 + b1*b1) + (b2*b2 + b3*b3)));
        }
        if (blockIdx.x == 0)
            for (int i = threadIdx.x; i < 512; i += 256)
                g_tab[i] = (lgammaf((float)i + 1.f) + (float)i) * LOG2E;
        __syncthreads();
        double tot = blk_reduce256(lp, sRed);
        if (threadIdx.x == 0) g_prior[blockIdx.x] = tot;
    }
}

// =========================================================================
// Pass 2: main NB likelihood, packed f32x2 hot loop, MLP-8 batched Y loads.
// grid (ceil(G/512), ceil(N/RP2)), 256 threads; thread owns 2 genes,
// 16 rows in two half-batches of 8 (loads front-batched per half-batch).
// Last block (ticket) folds partials + priors -> out[0].
// =========================================================================
template <bool VEC>
__global__ void __launch_bounds__(256, 4) k_pass2(
        const float* __restrict__ X, const float* __restrict__ Y,
        float* __restrict__ out, int N, int G, int NCHUNK, int nblocks) {
    __shared__ u64   sxd[RP2][5];   // per-row duplicated {x0,x0},..,{wn,wn}
    __shared__ float sT[512];
    __shared__ double sRed[8];
    __shared__ int    sLast;

    int t = threadIdx.x;
    int row0 = blockIdx.y * RP2;
    int rh   = min(RP2, N - row0);
    if (t < RP2) {
        int n = min(row0 + t, N - 1);
        float4 xv = ((const float4*)X)[n];
        float Z = 0.f, S = 0.f;
        for (int c = 0; c < NCHUNK; c++) {
            Z += g_Zp[c * N_MAX + n];
            S += g_Sp[c * N_MAX + n];
        }
        float wn = lg2a(S) - lg2a(Z);
        sxd[t][0] = pk2(xv.x, xv.x);
        sxd[t][1] = pk2(xv.y, xv.y);
        sxd[t][2] = pk2(xv.z, xv.z);
        sxd[t][3] = pk2(xv.w, xv.w);
        sxd[t][4] = pk2(wn, wn);
    }
    for (int i = t; i < 512; i += 256) sT[i] = g_tab[i];
    __syncthreads();

    int gp = (blockIdx.x * 256 + t) * 2;
    bool valid = gp < G;
    double d = 0.0;

    if (valid) {
        bool full = (gp + 1 < G);
        int gc1 = min(gp + 1, G - 1);
        float r0 = g_r[gp], r1 = g_r[gc1];

        {   // fold per-gene constants (base-2)
            float csum = g_C2[gp];
            if (full) csum += g_C2[gc1];
            d = (double)rh * (double)csum;
        }

        if (full && VEC && rh == RP2) {
            u64 P0 = pk2(g_q0[gp], g_q0[gc1]);
            u64 P1 = pk2(g_q1[gp], g_q1[gc1]);
            u64 P2 = pk2(g_q2[gp], g_q2[gc1]);
            u64 P3 = pk2(g_q3[gp], g_q3[gc1]);
            u64 M2 = pk2(g_mu2[gp], g_mu2[gc1]);
            u64 R2 = pk2(r0, r1);
            const u64 C1e = pk2(1.f, 1.f),  C2e = pk2(2.f, 2.f);
            const u64 C3e = pk2(3.f, 3.f),  C4e = pk2(4.f, 4.f);
            const u64 CHe = pk2(-0.5f, -0.5f), CSe = pk2(SER_K, SER_K);
            const u64 CN4e = pk2(-SHIFT4, -SHIFT4), CN1e = pk2(-1.f, -1.f);
            u64 acc2 = pk2(0.f, 0.f);
            const float* Yb = Y + (size_t)row0 * G + gp;

            #pragma unroll
            for (int h = 0; h < RP2 / HB; h++) {
                // front-batch HB independent row loads -> MLP = HB
                float2 yv[HB];
                #pragma unroll
                for (int i = 0; i < HB; i++)
                    yv[i] = *(const float2*)(Yb + (size_t)(h * HB + i) * G);

                #pragma unroll
                for (int i = 0; i < HB; i++) {
                    int rw = h * HB + i;
                    u64 y2 = pk2(yv[i].x, yv[i].y);
                    u64 tt2 = add2(fma2(sxd[rw][0], P0,
                                fma2(sxd[rw][1], P1,
                                fma2(sxd[rw][2], P2,
                                fma2(sxd[rw][3], P3, M2)))), sxd[rw][4]);
                    float t0, t1; upk2(tt2, t0, t1);
                    u64 lgrm = pk2(lg2a(r0 + ex2a(t0)), lg2a(r1 + ex2a(t1)));
                    u64 x2  = add2(y2, R2);
                    u64 p2  = mul2(mul2(x2, add2(x2, C1e)),
                                   mul2(add2(x2, C2e), add2(x2, C3e)));
                    float pA, pB; upk2(p2, pA, pB);
                    u64 lp2 = pk2(lg2a(pA), lg2a(pB));
                    u64 xs2 = add2(x2, C4e);
                    float xA, xB; upk2(xs2, xA, xB);
                    u64 z2   = pk2(rcpa(xA), rcpa(xB));
                    u64 lxs2 = pk2(lg2a(xA), lg2a(xB));
                    u64 extra2 = fma2(lp2, CN1e, CN4e);
                    u64 ser2   = fma2(z2, CSe, extra2);
                    u64 stir2  = fma2(add2(xs2, CHe), lxs2, ser2);
                    u64 sT2 = pk2(sT[(int)yv[i].x], sT[(int)yv[i].y]);
                    u64 res = sub2(stir2, sT2);
                    res = fma2(y2, tt2, res);
                    res = sub2(res, mul2(x2, lgrm));
                    acc2 = add2(acc2, res);
                }
            }
            float aLo, aHi; upk2(acc2, aLo, aHi);
            d += (double)aLo + (double)aHi;
        } else {
            // scalar tail path (ragged rows / genes / misaligned)
            for (int i = 0; i < rh; i++) {
                float xs[4], wns, dummy;
                upk2(sxd[i][0], xs[0], dummy);
                upk2(sxd[i][1], xs[1], dummy);
                upk2(sxd[i][2], xs[2], dummy);
                upk2(sxd[i][3], xs[3], dummy);
                upk2(sxd[i][4], wns, dummy);
                const float* Yp = Y + (size_t)(row0 + i) * G;
                float e0 = nb_elem_s(xs, wns, Yp[gp],
                                     g_q0[gp], g_q1[gp], g_q2[gp], g_q3[gp],
                                     g_mu2[gp], r0, sT);
                d += (double)e0;
                if (full) {
                    float e1 = nb_elem_s(xs, wns, Yp[gc1],
                                         g_q0[gc1], g_q1[gc1], g_q2[gc1], g_q3[gc1],
                                         g_mu2[gc1], r1, sT);
                    d += (double)e1;
                }
            }
        }
        d *= LN2;                         // back to nats
    }

    double bsum = blk_reduce256(d, sRed);
    int bid = blockIdx.y * gridDim.x + blockIdx.x;
    if (t == 0) {
        g_part[bid] = bsum;
        __threadfence();
        unsigned old = atomicAdd(&g_ticket, 1u);
        sLast = ((old % (unsigned)nblocks) == (unsigned)(nblocks - 1));
    }
    __syncthreads();

    if (sLast) {
        double s = 0.0;
        for (int i = t; i < nblocks; i += 256) s += g_part[i];
        for (int c = t; c < NCHUNK; c += 256) s += g_prior[c];
        __syncthreads();
        double tot = blk_reduce256(s, sRed);
        if (t == 0) out[0] = (float)tot;
    }
}

extern "C" void kernel_launch(void* const* d_in, const int* in_sizes, int n_in,
                              void* d_out, int out_size) {
    const float* X    = (const float*)d_in[0];
    const float* Y    = (const float*)d_in[1];
    const float* mu   = (const float*)d_in[2];
    const float* beta = (const float*)d_in[3];
    const float* phi  = (const float*)d_in[4];
    float* out = (float*)d_out;

    int G = in_sizes[2];          // 20000
    int N = in_sizes[1] / G;      // 1024

    int NCHUNK = (G + CH - 1) / CH;
    bool vec = ((G & 3) == 0) && ((((unsigned long long)Y) & 15ull) == 0ull);

    dim3 g1(NCHUNK, (N + 31) / 32);
    if (vec) k_pass1<true><<<g1, 256>>>(X, Y, mu, beta, phi, N, G);
    else     k_pass1<false><<<g1, 256>>>(X, Y, mu, beta, phi, N, G);

    int gx2 = (G + 511) / 512;
    int gy2 = (N + RP2 - 1) / RP2;
    int nb  = gx2 * gy2;          // 40*64 = 2560 <= MAX_B2
    dim3 g2(gx2, gy2);
    if (vec) k_pass2<true><<<g2, 256>>>(X, Y, out, N, G, NCHUNK, nb);
    else     k_pass2<false><<<g2, 256>>>(X, Y, out, N, G, NCHUNK, nb);
}

// round 14
// speedup vs baseline: 1.1812x; 1.0305x over previous
#include <cuda_runtime.h>
#include <math.h>
#include <stdint.h>

// Fixed dataset shapes: N=1024, P=4, G=20000 (tolerates N%32==0, P==4, G<=G_MAX)
#define G_MAX 20480
#define N_MAX 1024
#define CH    512          // genes per pass1 chunk
#define NC_MAX 48          // max gene chunks
#define RP2   16           // rows per pass2 block
#define HB    4            // rows batched per load group (MLP)
#define MAX_B2 8192        // max pass2 blocks

// ---- device scratch (static; no allocations) ----
__device__ __align__(16) float g_r[G_MAX];     // 1/softplus(phi)  (raw)
__device__ __align__(16) float g_C2[G_MAX];    // per-gene const, base-2 units
__device__ __align__(16) float g_mu2[G_MAX];   // mu * log2e
__device__ __align__(16) float g_q0[G_MAX];    // beta rows * log2e
__device__ __align__(16) float g_q1[G_MAX];
__device__ __align__(16) float g_q2[G_MAX];
__device__ __align__(16) float g_q3[G_MAX];
__device__ float  g_tab[512];                  // (lgamma(k+1)+k) * log2e
__device__ float  g_Zp[NC_MAX * N_MAX];        // per-(chunk,row) sum exp(lu)
__device__ float  g_Sp[NC_MAX * N_MAX];        // per-(chunk,row) sum Y
__device__ double g_prior[NC_MAX];             // per-chunk prior partial (nats)
__device__ double g_part[MAX_B2];              // per-pass2-block partial (nats)
__device__ unsigned g_ticket;                  // monotone ticket (mod #blocks)

#define NORM_CONST   1.6120857137646180f       // 0.5*log(8*pi), s=2 normal prior
#define HALF_LOG_2PI 0.9189385332046727f
#define LOG2E        1.4426950408889634f
#define LN2          0.6931471805599453
#define SER_K        0.12022458674074694f      // LOG2E / 12
#define SHIFT4       5.7707801635558537f       // 4 * LOG2E

// raw MUFU ops
__device__ __forceinline__ float ex2a(float a){ float r; asm("ex2.approx.ftz.f32 %0,%1;":"=f"(r):"f"(a)); return r; }
__device__ __forceinline__ float lg2a(float a){ float r; asm("lg2.approx.ftz.f32 %0,%1;":"=f"(r):"f"(a)); return r; }
__device__ __forceinline__ float rcpa(float a){ float r; asm("rcp.approx.ftz.f32 %0,%1;":"=f"(r):"f"(a)); return r; }

// packed f32x2 ops (sm_103a)
typedef unsigned long long u64;
__device__ __forceinline__ u64 pk2(float lo, float hi){ u64 r; asm("mov.b64 %0,{%1,%2};":"=l"(r):"f"(lo),"f"(hi)); return r; }
__device__ __forceinline__ void upk2(u64 v, float& lo, float& hi){ asm("mov.b64 {%0,%1},%2;":"=f"(lo),"=f"(hi):"l"(v)); }
__device__ __forceinline__ u64 fma2(u64 a,u64 b,u64 c){ u64 r; asm("fma.rn.f32x2 %0,%1,%2,%3;":"=l"(r):"l"(a),"l"(b),"l"(c)); return r; }
__device__ __forceinline__ u64 add2(u64 a,u64 b){ u64 r; asm("add.rn.f32x2 %0,%1,%2;":"=l"(r):"l"(a),"l"(b)); return r; }
__device__ __forceinline__ u64 sub2(u64 a,u64 b){ u64 r; asm("sub.rn.f32x2 %0,%1,%2;":"=l"(r):"l"(a),"l"(b)); return r; }
__device__ __forceinline__ u64 mul2(u64 a,u64 b){ u64 r; asm("mul.rn.f32x2 %0,%1,%2;":"=l"(r):"l"(a),"l"(b)); return r; }

// ---- block reduce for double (256 threads) ----
__device__ __forceinline__ double blk_reduce256(double v, double* sRed) {
    int t = threadIdx.x, lane = t & 31, wid = t >> 5;
    #pragma unroll
    for (int off = 16; off; off >>= 1)
        v += __shfl_down_sync(0xffffffffu, v, off);
    if (lane == 0) sRed[wid] = v;
    __syncthreads();
    if (t < 8) {
        v = sRed[t];
        #pragma unroll
        for (int off = 4; off; off >>= 1)
            v += __shfl_down_sync(0x000000ffu, v, off);
    }
    return v;  // valid in thread 0
}

// ---- scalar NB core (tail path), always-shift Stirling, base-2 units ----
__device__ __forceinline__ float nb_elem_s(const float* xr, float wn, float y,
                                           float b0, float b1, float b2, float b3,
                                           float mug, float r,
                                           const float* __restrict__ sT) {
    float tt = fmaf(xr[0], b0, fmaf(xr[1], b1, fmaf(xr[2], b2, fmaf(xr[3], b3, mug)))) + wn;
    float m  = ex2a(tt);
    float lg = lg2a(r + m);
    float x  = y + r;
    float p  = (x * (x + 1.f)) * ((x + 2.f) * (x + 3.f));
    float xs = x + 4.f;
    float extra = -lg2a(p) - SHIFT4;
    float z  = rcpa(xs);
    float stir = fmaf(xs - 0.5f, lg2a(xs), fmaf(z, SER_K, extra));
    return stir - sT[(int)y] + fmaf(y, tt, -x * lg);
}

// =========================================================================
// Pass 1: per-(chunk,row) sumexp(lu) and sum(Y); by==0 blocks also do the
// per-gene setup (r, C2, scaled params), priors, and the lgamma table.
// grid (NCHUNK, N/32), 256 threads; warp w owns rows by*32 + 4w .. +3
// =========================================================================
template <bool VEC>
__global__ void __launch_bounds__(256) k_pass1(
        const float* __restrict__ X, const float* __restrict__ Y,
        const float* __restrict__ mu, const float* __restrict__ beta,
        const float* __restrict__ phi, int N, int G) {
    __shared__ float smu[CH], sb0[CH], sb1[CH], sb2[CH], sb3[CH];
    __shared__ double sRed[8];

    int gbase = blockIdx.x * CH;
    int gmax  = min(CH, G - gbase);
    for (int i = threadIdx.x; i < CH; i += 256) {
        int g = gbase + i;
        bool v = (i < gmax);
        smu[i] = v ? __ldg(mu + g)         * LOG2E : -1e30f;
        sb0[i] = v ? __ldg(beta + g)       * LOG2E : 0.f;
        sb1[i] = v ? __ldg(beta + G + g)   * LOG2E : 0.f;
        sb2[i] = v ? __ldg(beta + 2*G + g) * LOG2E : 0.f;
        sb3[i] = v ? __ldg(beta + 3*G + g) * LOG2E : 0.f;
    }
    __syncthreads();

    int w = threadIdx.x >> 5, lane = threadIdx.x & 31;
    int n0 = blockIdx.y * 32 + w * 4;
    const float4* X4 = (const float4*)X;
    float4 xr[4];
    const float* Yr[4];
    #pragma unroll
    for (int r = 0; r < 4; r++) {
        int n = min(n0 + r, N - 1);
        xr[r] = X4[n];
        Yr[r] = Y + (size_t)n * G + gbase;
    }

    float ae[4] = {0.f, 0.f, 0.f, 0.f};
    float ay[4] = {0.f, 0.f, 0.f, 0.f};

    #pragma unroll 2
    for (int it = 0; it < CH / 128; it++) {
        int j  = it * 32 + lane;
        int g4 = j * 4;
        float4 m4 = ((const float4*)smu)[j];
        float4 a0 = ((const float4*)sb0)[j];
        float4 a1 = ((const float4*)sb1)[j];
        float4 a2 = ((const float4*)sb2)[j];
        float4 a3 = ((const float4*)sb3)[j];
        #pragma unroll
        for (int r = 0; r < 4; r++) {
            float4 y;
            if (g4 + 3 < gmax) {
                if (VEC) y = *(const float4*)(Yr[r] + g4);
                else { y.x = Yr[r][g4]; y.y = Yr[r][g4+1];
                       y.z = Yr[r][g4+2]; y.w = Yr[r][g4+3]; }
            } else {
                y.x = (g4+0 < gmax) ? Yr[r][g4+0] : 0.f;
                y.y = (g4+1 < gmax) ? Yr[r][g4+1] : 0.f;
                y.z = (g4+2 < gmax) ? Yr[r][g4+2] : 0.f;
                y.w = (g4+3 < gmax) ? Yr[r][g4+3] : 0.f;
            }
            float l0 = fmaf(xr[r].x, a0.x, fmaf(xr[r].y, a1.x, fmaf(xr[r].z, a2.x, fmaf(xr[r].w, a3.x, m4.x))));
            float l1 = fmaf(xr[r].x, a0.y, fmaf(xr[r].y, a1.y, fmaf(xr[r].z, a2.y, fmaf(xr[r].w, a3.y, m4.y))));
            float l2 = fmaf(xr[r].x, a0.z, fmaf(xr[r].y, a1.z, fmaf(xr[r].z, a2.z, fmaf(xr[r].w, a3.z, m4.z))));
            float l3 = fmaf(xr[r].x, a0.w, fmaf(xr[r].y, a1.w, fmaf(xr[r].z, a2.w, fmaf(xr[r].w, a3.w, m4.w))));
            ae[r] += (ex2a(l0) + ex2a(l1)) + (ex2a(l2) + ex2a(l3));
            ay[r] += (y.x + y.y) + (y.z + y.w);
        }
    }

    #pragma unroll
    for (int r = 0; r < 4; r++) {
        float e = ae[r], s = ay[r];
        #pragma unroll
        for (int off = 16; off; off >>= 1) {
            e += __shfl_down_sync(0xffffffffu, e, off);
            s += __shfl_down_sync(0xffffffffu, s, off);
        }
        if (lane == 0 && n0 + r < N) {
            g_Zp[blockIdx.x * N_MAX + n0 + r] = e;
            g_Sp[blockIdx.x * N_MAX + n0 + r] = s;
        }
    }

    // ---- setup + priors (one row-block per chunk) ----
    if (blockIdx.y == 0) {
        double lp = 0.0;
        for (int i = threadIdx.x; i < gmax; i += 256) {
            int g = gbase + i;
            float ph = __ldg(phi + g);
            float sp = fmaxf(ph, 0.f) + log1pf(expf(-fabsf(ph)));  // softplus
            float r  = 1.f / sp;
            g_r[g]   = r;
            g_C2[g]  = (r * logf(r) - lgammaf(r) - r + HALF_LOG_2PI) * LOG2E;
            g_mu2[g] = smu[i];            // already * log2e
            g_q0[g]  = sb0[i];
            g_q1[g]  = sb1[i];
            g_q2[g]  = sb2[i];
            g_q3[g]  = sb3[i];
            float m  = __ldg(mu + g);
            float b0 = __ldg(beta + g),       b1 = __ldg(beta + G + g);
            float b2 = __ldg(beta + 2*G + g), b3 = __ldg(beta + 3*G + g);
            lp += (double)(logf(sp) - sp - NORM_CONST - 0.125f * m * m);
            lp += (double)(-4.f * NORM_CONST
                           - 0.125f * ((b0*b0 + b1*b1) + (b2*b2 + b3*b3)));
        }
        if (blockIdx.x == 0)
            for (int i = threadIdx.x; i < 512; i += 256)
                g_tab[i] = (lgammaf((float)i + 1.f) + (float)i) * LOG2E;
        __syncthreads();
        double tot = blk_reduce256(lp, sRed);
        if (threadIdx.x == 0) g_prior[blockIdx.x] = tot;
    }
}

// =========================================================================
// Pass 2: main NB likelihood, packed f32x2 hot loop, register-dieted for
// 6 blocks/SM occupancy. grid (ceil(G/512), ceil(N/RP2)), 256 threads;
// thread owns 2 genes, 16 rows in four batches of HB=4 (MLP 4).
// Last block (ticket) folds partials + priors -> out[0].
// =========================================================================
template <bool VEC>
__global__ void __launch_bounds__(256, 6) k_pass2(
        const float* __restrict__ X, const float* __restrict__ Y,
        float* __restrict__ out, int N, int G, int NCHUNK, int nblocks) {
    __shared__ u64   sxd[RP2][5];   // per-row duplicated {x0,x0},..,{wn,wn}
    __shared__ float sT[512];
    __shared__ double sRed[8];
    __shared__ int    sLast;

    int t = threadIdx.x;
    int row0 = blockIdx.y * RP2;
    int rh   = min(RP2, N - row0);
    if (t < RP2) {
        int n = min(row0 + t, N - 1);
        float4 xv = ((const float4*)X)[n];
        float Z = 0.f, S = 0.f;
        for (int c = 0; c < NCHUNK; c++) {
            Z += g_Zp[c * N_MAX + n];
            S += g_Sp[c * N_MAX + n];
        }
        float wn = lg2a(S) - lg2a(Z);
        sxd[t][0] = pk2(xv.x, xv.x);
        sxd[t][1] = pk2(xv.y, xv.y);
        sxd[t][2] = pk2(xv.z, xv.z);
        sxd[t][3] = pk2(xv.w, xv.w);
        sxd[t][4] = pk2(wn, wn);
    }
    for (int i = t; i < 512; i += 256) sT[i] = g_tab[i];
    __syncthreads();

    int gp = (blockIdx.x * 256 + t) * 2;
    bool valid = gp < G;
    double d = 0.0;

    if (valid) {
        bool full = (gp + 1 < G);
        int gc1 = min(gp + 1, G - 1);
        float r0 = g_r[gp], r1 = g_r[gc1];

        {   // fold per-gene constants (base-2)
            float csum = g_C2[gp];
            if (full) csum += g_C2[gc1];
            d = (double)rh * (double)csum;
        }

        if (full && VEC && rh == RP2) {
            u64 P0 = pk2(g_q0[gp], g_q0[gc1]);
            u64 P1 = pk2(g_q1[gp], g_q1[gc1]);
            u64 P2 = pk2(g_q2[gp], g_q2[gc1]);
            u64 P3 = pk2(g_q3[gp], g_q3[gc1]);
            u64 M2 = pk2(g_mu2[gp], g_mu2[gc1]);
            u64 R2 = pk2(r0, r1);
            // 6 packed constants (trimmed set)
            const u64 C2e = pk2(2.f, 2.f), C3e = pk2(3.f, 3.f);
            const u64 C4e = pk2(4.f, 4.f), CHe = pk2(-0.5f, -0.5f);
            const u64 CSe = pk2(SER_K, SER_K), CN4e = pk2(-SHIFT4, -SHIFT4);
            u64 acc2 = pk2(0.f, 0.f);
            const float* Yb = Y + (size_t)row0 * G + gp;

            #pragma unroll
            for (int h = 0; h < RP2 / HB; h++) {
                // front-batch HB independent row loads -> MLP = HB
                float2 yv[HB];
                #pragma unroll
                for (int i = 0; i < HB; i++)
                    yv[i] = *(const float2*)(Yb + (size_t)(h * HB + i) * G);

                #pragma unroll
                for (int i = 0; i < HB; i++) {
                    int rw = h * HB + i;
                    u64 y2 = pk2(yv[i].x, yv[i].y);
                    u64 tt2 = fma2(sxd[rw][0], P0,
                              fma2(sxd[rw][1], P1,
                              fma2(sxd[rw][2], P2,
                              fma2(sxd[rw][3], P3, add2(M2, sxd[rw][4])))));
                    float t0, t1; upk2(tt2, t0, t1);
                    u64 lgrm = pk2(lg2a(r0 + ex2a(t0)), lg2a(r1 + ex2a(t1)));
                    u64 x2 = add2(y2, R2);
                    u64 q2 = mul2(x2, add2(x2, C3e));      // x^2 + 3x
                    u64 p2 = mul2(q2, add2(q2, C2e));      // x(x+1)(x+2)(x+3)
                    float pA, pB; upk2(p2, pA, pB);
                    u64 xs2 = add2(x2, C4e);
                    float xA, xB; upk2(xs2, xA, xB);
                    u64 z2   = pk2(rcpa(xA), rcpa(xB));
                    u64 lxs2 = pk2(lg2a(xA), lg2a(xB));
                    u64 extra2 = sub2(CN4e, pk2(lg2a(pA), lg2a(pB)));
                    u64 ser2   = fma2(z2, CSe, extra2);
                    u64 stir2  = fma2(add2(xs2, CHe), lxs2, ser2);
                    u64 sT2 = pk2(sT[(int)yv[i].x], sT[(int)yv[i].y]);
                    u64 res = fma2(y2, tt2, sub2(stir2, sT2));
                    res = sub2(res, mul2(x2, lgrm));
                    acc2 = add2(acc2, res);
                }
            }
            float aLo, aHi; upk2(acc2, aLo, aHi);
            d += (double)aLo + (double)aHi;
        } else {
            // scalar tail path (ragged rows / genes / misaligned)
            for (int i = 0; i < rh; i++) {
                float xs[4], wns, dummy;
                upk2(sxd[i][0], xs[0], dummy);
                upk2(sxd[i][1], xs[1], dummy);
                upk2(sxd[i][2], xs[2], dummy);
                upk2(sxd[i][3], xs[3], dummy);
                upk2(sxd[i][4], wns, dummy);
                const float* Yp = Y + (size_t)(row0 + i) * G;
                float e0 = nb_elem_s(xs, wns, Yp[gp],
                                     g_q0[gp], g_q1[gp], g_q2[gp], g_q3[gp],
                                     g_mu2[gp], r0, sT);
                d += (double)e0;
                if (full) {
                    float e1 = nb_elem_s(xs, wns, Yp[gc1],
                                         g_q0[gc1], g_q1[gc1], g_q2[gc1], g_q3[gc1],
                                         g_mu2[gc1], r1, sT);
                    d += (double)e1;
                }
            }
        }
        d *= LN2;                         // back to nats
    }

    double bsum = blk_reduce256(d, sRed);
    int bid = blockIdx.y * gridDim.x + blockIdx.x;
    if (t == 0) {
        g_part[bid] = bsum;
        __threadfence();
        unsigned old = atomicAdd(&g_ticket, 1u);
        sLast = ((old % (unsigned)nblocks) == (unsigned)(nblocks - 1));
    }
    __syncthreads();

    if (sLast) {
        double s = 0.0;
        for (int i = t; i < nblocks; i += 256) s += g_part[i];
        for (int c = t; c < NCHUNK; c += 256) s += g_prior[c];
        __syncthreads();
        double tot = blk_reduce256(s, sRed);
        if (t == 0) out[0] = (float)tot;
    }
}

extern "C" void kernel_launch(void* const* d_in, const int* in_sizes, int n_in,
                              void* d_out, int out_size) {
    const float* X    = (const float*)d_in[0];
    const float* Y    = (const float*)d_in[1];
    const float* mu   = (const float*)d_in[2];
    const float* beta = (const float*)d_in[3];
    const float* phi  = (const float*)d_in[4];
    float* out = (float*)d_out;

    int G = in_sizes[2];          // 20000
    int N = in_sizes[1] / G;      // 1024

    int NCHUNK = (G + CH - 1) / CH;
    bool vec = ((G & 3) == 0) && ((((unsigned long long)Y) & 15ull) == 0ull);

    dim3 g1(NCHUNK, (N + 31) / 32);
    if (vec) k_pass1<true><<<g1, 256>>>(X, Y, mu, beta, phi, N, G);
    else     k_pass1<false><<<g1, 256>>>(X, Y, mu, beta, phi, N, G);

    int gx2 = (G + 511) / 512;
    int gy2 = (N + RP2 - 1) / RP2;
    int nb  = gx2 * gy2;          // 40*64 = 2560 <= MAX_B2
    dim3 g2(gx2, gy2);
    if (vec) k_pass2<true><<<g2, 256>>>(X, Y, out, N, G, NCHUNK, nb);
    else     k_pass2<false><<<g2, 256>>>(X, Y, out, N, G, NCHUNK, nb);
}